// round 1
// baseline (speedup 1.0000x reference)
#include <cuda_runtime.h>

#define FS 4096
#define FT 4096
#define NPTS (FS * 8)
#define NBLK 128
#define TPB 256

// Scratch (allocation-free: __device__ globals)
__device__ float4 g_src_bc[FS];      // xyz, w = 0.5*|bc|^2
__device__ float4 g_tgt_bc[FT];      // xyz, w = 0.5*|bc|^2
__device__ float4 g_pts[NPTS];       // xyz, w = |pt|^2
__device__ float  g_fwd_partial[NBLK];
__device__ float  g_rev_partial[NBLK];

// ---------------------------------------------------------------------------
// Kernel 1: barycenters + sampled points (independent computations)
// ---------------------------------------------------------------------------
__global__ void prep_kernel(const float* __restrict__ sv, const int* __restrict__ sf,
                            const float* __restrict__ tv, const int* __restrict__ tf,
                            const float* __restrict__ r1u, const float* __restrict__ r2u) {
    int i = blockIdx.x * blockDim.x + threadIdx.x;
    if (i < FS) {
        // source barycenter (source_faces is [FS,3] row-major)
        int a = sf[3*i+0], b = sf[3*i+1], c = sf[3*i+2];
        float x = (sv[3*a+0] + sv[3*b+0] + sv[3*c+0]) * (1.0f/3.0f);
        float y = (sv[3*a+1] + sv[3*b+1] + sv[3*c+1]) * (1.0f/3.0f);
        float z = (sv[3*a+2] + sv[3*b+2] + sv[3*c+2]) * (1.0f/3.0f);
        g_src_bc[i] = make_float4(x, y, z, 0.5f*(x*x + y*y + z*z));
        // target barycenter (target_faces is [3,FT] row-major, transposed use)
        int ta = tf[i], tb = tf[FT + i], tc = tf[2*FT + i];
        float tx = (tv[3*ta+0] + tv[3*tb+0] + tv[3*tc+0]) * (1.0f/3.0f);
        float ty = (tv[3*ta+1] + tv[3*tb+1] + tv[3*tc+1]) * (1.0f/3.0f);
        float tz = (tv[3*ta+2] + tv[3*tb+2] + tv[3*tc+2]) * (1.0f/3.0f);
        g_tgt_bc[i] = make_float4(tx, ty, tz, 0.5f*(tx*tx + ty*ty + tz*tz));
    }
    if (i < NPTS) {
        int f = i >> 3;  // pt_faces = repeat(arange(Fs), 8)
        int a = sf[3*f+0], b = sf[3*f+1], c = sf[3*f+2];
        float r1 = sqrtf(r1u[i]);   // r1u is [FS,8] row-major -> flat index i
        float r2 = r2u[i];
        float w1 = 1.0f - r1;
        float w2 = r1 * (1.0f - r2);
        float w3 = r1 * r2;
        float x = w1*sv[3*a+0] + w2*sv[3*b+0] + w3*sv[3*c+0];
        float y = w1*sv[3*a+1] + w2*sv[3*b+1] + w3*sv[3*c+1];
        float z = w1*sv[3*a+2] + w2*sv[3*b+2] + w3*sv[3*c+2];
        g_pts[i] = make_float4(x, y, z, x*x + y*y + z*z);  // full norm here
    }
}

// ---------------------------------------------------------------------------
// Kernel 2: forward loss. 8 lanes per source face, each covers FT/8 targets
// with lane-major stride (j = chunk + 8t) -> conflict-free shared reads.
// ---------------------------------------------------------------------------
__global__ void fwd_kernel(const float* __restrict__ probs) {
    extern __shared__ float4 s_tgt[];   // FT float4 = 64 KB
    int tid = threadIdx.x;
    for (int k = tid; k < FT; k += TPB) s_tgt[k] = g_tgt_bc[k];
    __syncthreads();

    int gid   = blockIdx.x * TPB + tid;   // 0..32767
    int face  = gid >> 3;
    int chunk = gid & 7;
    float4 p  = g_src_bc[face];           // p.w = 0.5*|p|^2

    float beste = 1e30f;
    #pragma unroll 8
    for (int t = 0; t < FT/8; t++) {
        float4 q  = s_tgt[chunk + 8*t];
        float dot = fmaf(p.x, q.x, fmaf(p.y, q.y, p.z*q.z));
        beste = fminf(beste, q.w - dot);  // e = 0.5|q|^2 - p.q ; d = 2(p.w + e)
    }
    beste = fminf(beste, __shfl_xor_sync(0xffffffffu, beste, 1));
    beste = fminf(beste, __shfl_xor_sync(0xffffffffu, beste, 2));
    beste = fminf(beste, __shfl_xor_sync(0xffffffffu, beste, 4));

    float contrib = 0.0f;
    if (chunk == 0) {
        float d = fmaxf(2.0f * (p.w + beste), 0.0f);
        contrib = probs[face] * d;
    }
    __shared__ float red[TPB];
    red[tid] = contrib;
    __syncthreads();
    #pragma unroll
    for (int s = TPB/2; s > 0; s >>= 1) {
        if (tid < s) red[tid] += red[tid + s];
        __syncthreads();
    }
    if (tid == 0) g_fwd_partial[blockIdx.x] = red[0];
}

// ---------------------------------------------------------------------------
// Kernel 3: reverse loss. One thread per sampled point. Top-6 over src_bc
// (with indices, self-exclusion) + min over tgt_bc. All candidates in smem,
// warp-uniform index -> LDS broadcast.
// ---------------------------------------------------------------------------
__global__ void rev_kernel(const float* __restrict__ probs) {
    extern __shared__ char smem_raw[];
    float4* s_src = (float4*)smem_raw;          // FS  (64 KB)
    float4* s_tgt = s_src + FS;                 // FT  (64 KB)
    float*  s_pr  = (float*)(s_tgt + FT);       // FS  (16 KB)

    int tid = threadIdx.x;
    for (int k = tid; k < FS; k += TPB) {
        s_src[k] = g_src_bc[k];
        s_tgt[k] = g_tgt_bc[k];
        s_pr[k]  = probs[k];
    }
    __syncthreads();

    int i     = blockIdx.x * TPB + tid;   // point id
    float4 p  = g_pts[i];                 // p.w = full |p|^2
    int sface = i >> 3;

    // top-6 smallest e over source barycenters (ascending, stable ties->lower j)
    float be[6]; int bi6[6];
    #pragma unroll
    for (int k = 0; k < 6; k++) { be[k] = 1e30f; bi6[k] = -1; }

    #pragma unroll 4
    for (int j = 0; j < FS; j++) {
        float4 q  = s_src[j];
        float dot = fmaf(p.x, q.x, fmaf(p.y, q.y, p.z*q.z));
        float e   = q.w - dot;
        if (e < be[5]) {               // rare: ~50/4096 per point
            be[5] = e; bi6[5] = j;
            #pragma unroll
            for (int k = 5; k > 0; --k) {
                if (be[k] < be[k-1]) {
                    float te = be[k]; be[k] = be[k-1]; be[k-1] = te;
                    int   ti = bi6[k]; bi6[k] = bi6[k-1]; bi6[k-1] = ti;
                }
            }
        }
    }

    // min over target barycenters
    float mte = 1e30f;
    #pragma unroll 8
    for (int j = 0; j < FT; j++) {
        float4 q  = s_tgt[j];
        float dot = fmaf(p.x, q.x, fmaf(p.y, q.y, p.z*q.z));
        mte = fminf(mte, q.w - dot);
    }

    // self-exclusion: drop own-face entry if in top-6, else use 5 smallest
    int selfpos = 6;
    #pragma unroll
    for (int k = 0; k < 6; k++) if (bi6[k] == sface) selfpos = k;
    float s5 = 0.0f;
    #pragma unroll
    for (int k = 0; k < 6; k++) {
        bool inc = (k != selfpos) && (k < 5 || selfpos <= 5);
        if (inc) {
            float d = fmaxf(fmaf(2.0f, be[k], p.w), 0.0f);
            s5 += s_pr[bi6[k]] * d;
        }
    }
    float pp   = s_pr[sface];
    float mind = fmaxf(fmaf(2.0f, mte, p.w), 0.0f);
    float val  = fmaf(pp, mind, (1.0f - pp) * (s5 * 0.2f));

    __shared__ float red[TPB];
    red[tid] = val;
    __syncthreads();
    #pragma unroll
    for (int s = TPB/2; s > 0; s >>= 1) {
        if (tid < s) red[tid] += red[tid + s];
        __syncthreads();
    }
    if (tid == 0) g_rev_partial[blockIdx.x] = red[0];
}

// ---------------------------------------------------------------------------
// Kernel 4: deterministic final reduction
// ---------------------------------------------------------------------------
__global__ void final_kernel(float* __restrict__ out) {
    __shared__ float red[TPB];
    int t = threadIdx.x;
    float v = 0.0f;
    if (t < NBLK) v = g_fwd_partial[t] + g_rev_partial[t];
    red[t] = v;
    __syncthreads();
    #pragma unroll
    for (int s = TPB/2; s > 0; s >>= 1) {
        if (t < s) red[t] += red[t + s];
        __syncthreads();
    }
    if (t == 0) out[0] = red[0];
}

extern "C" void kernel_launch(void* const* d_in, const int* in_sizes, int n_in,
                              void* d_out, int out_size) {
    const float* sv    = (const float*)d_in[0];  // (1,2048,3)
    const int*   sf    = (const int*)  d_in[1];  // (4096,3)
    const float* tv    = (const float*)d_in[2];  // (1,2048,3)
    const int*   tf    = (const int*)  d_in[3];  // (3,4096)
    const float* probs = (const float*)d_in[4];  // (4096,)
    const float* r1u   = (const float*)d_in[5];  // (4096,8)
    const float* r2u   = (const float*)d_in[6];  // (4096,8)

    const size_t fwd_smem = (size_t)FT * sizeof(float4);
    const size_t rev_smem = (size_t)(FS + FT) * sizeof(float4) + (size_t)FS * sizeof(float);
    cudaFuncSetAttribute(fwd_kernel, cudaFuncAttributeMaxDynamicSharedMemorySize, (int)fwd_smem);
    cudaFuncSetAttribute(rev_kernel, cudaFuncAttributeMaxDynamicSharedMemorySize, (int)rev_smem);

    prep_kernel<<<NPTS / TPB, TPB>>>(sv, sf, tv, tf, r1u, r2u);
    fwd_kernel <<<NBLK, TPB, fwd_smem>>>(probs);
    rev_kernel <<<NBLK, TPB, rev_smem>>>(probs);
    final_kernel<<<1, TPB>>>((float*)d_out);
}